// round 17
// baseline (speedup 1.0000x reference)
#include <cuda_runtime.h>

#define B_  16
#define C_  8
#define H_  512
#define W_  512
#define TW  32           // tile width
#define TH  16           // tile height
#define HH_ 18           // TH + 2 (halo rows)
#define SROW 36          // smem row stride (floats); in-tile cols at wx 2..33
#define PLANE (C_ * HH_ * SROW)          /* 5184 floats */
#define NTHREADS 256
#define NBLOCKS ((W_/TW)*(H_/TH)*B_)     /* 8192 */
#define CHS ((size_t)H_ * W_)            /* channel stride */

__device__ double   g_acc;    // zero-initialized at module load
__device__ unsigned g_tick;   // zero-initialized at module load

__device__ __forceinline__ void sigmoid_pair(float x, float& p, float& lp) {
    float e  = __expf(-fabsf(x));            // EX2
    float op = 1.0f + e;
    float l  = __logf(op);                   // LG2 (= log1p(e), e<=1)
    float r  = __fdividef(1.0f, op);         // RCP
    p  = (x >= 0.0f) ? r : e * r;            // sigmoid(x)
    lp = fminf(x, 0.0f) - l;                 // log sigmoid(x)
}

__global__ __launch_bounds__(NTHREADS, 5)
void k_main(const float* __restrict__ cmap,
            const float* __restrict__ target,
            const float* __restrict__ con,
            float* __restrict__ out) {
    __shared__ float s_p[PLANE];                // sigmoid(x)
    __shared__ float s_lp[PLANE];               // log sigmoid(x)
    __shared__ unsigned char s_mask[TH * TW];   // packed con bits per pixel

    const int w0  = blockIdx.x * TW;
    const int h0  = blockIdx.y * TH;
    const int b   = blockIdx.z;
    const int tid = threadIdx.x;
    const int lane = tid & 31;
    const int wrp  = tid >> 5;     // 0..7

    float acc08 = 0.0f;   // conmap BCE terms (weight 0.8 applied at end)
    float acc02 = 0.0f;   // bimap/vote BCE terms (weight 0.2 at end)
    float acc1  = 0.0f;   // decouple terms

    // ==== load phase: job = (halo row, 4-col group), all 8 channels.
    // float4 LDG (coalesced 128B/8 lanes), float2 STS. Conmap BCE fused while
    // x,lp live:  t*logp+(1-t)*log1mp = lp - (1-t)*x  (exact; clip dead,
    // |x| << 100). Con bitmask accumulated in registers (thread owns its 4 px
    // across all channels).
    if (tid < HH_ * 8) {
        const int row = tid >> 3;          // halo row 0..17
        const int g   = tid & 7;           // col group 0..7
        const int gh  = h0 - 1 + row;
        const bool inimg  = (unsigned)gh < H_;
        const bool intile = (row >= 1) && (row <= TH);
        const long goff = ((long)(b * C_) * H_ + gh) * W_ + (w0 + 4 * g);
        unsigned m0 = 0, m1 = 0, m2 = 0, m3 = 0;
        #pragma unroll
        for (int c = 0; c < 8; c++) {
            float4 p4  = make_float4(0.f, 0.f, 0.f, 0.f);
            float4 lp4 = make_float4(-1e9f, -1e9f, -1e9f, -1e9f);
            if (inimg) {
                float4 x4 = *(const float4*)(cmap + goff + (long)c * (long)CHS);
                sigmoid_pair(x4.x, p4.x, lp4.x);
                sigmoid_pair(x4.y, p4.y, lp4.y);
                sigmoid_pair(x4.z, p4.z, lp4.z);
                sigmoid_pair(x4.w, p4.w, lp4.w);
                if (intile) {
                    float4 t4 = __ldcs((const float4*)(con + goff
                                       + (long)c * (long)CHS));
                    m0 |= (t4.x != 0.0f ? 1u : 0u) << c;
                    m1 |= (t4.y != 0.0f ? 1u : 0u) << c;
                    m2 |= (t4.z != 0.0f ? 1u : 0u) << c;
                    m3 |= (t4.w != 0.0f ? 1u : 0u) << c;
                    acc08 += fmaf(t4.x - 1.0f, x4.x, lp4.x);
                    acc08 += fmaf(t4.y - 1.0f, x4.y, lp4.y);
                    acc08 += fmaf(t4.z - 1.0f, x4.z, lp4.z);
                    acc08 += fmaf(t4.w - 1.0f, x4.w, lp4.w);
                }
            }
            const int si = (c * HH_ + row) * SROW + 2 + 4 * g;  // even: STS.64 ok
            *(float2*)&s_p[si]      = make_float2(p4.x, p4.y);
            *(float2*)&s_p[si + 2]  = make_float2(p4.z, p4.w);
            *(float2*)&s_lp[si]     = make_float2(lp4.x, lp4.y);
            *(float2*)&s_lp[si + 2] = make_float2(lp4.z, lp4.w);
        }
        if (intile)
            *(uchar4*)&s_mask[(row - 1) * TW + 4 * g] =
                make_uchar4((unsigned char)m0, (unsigned char)m1,
                            (unsigned char)m2, (unsigned char)m3);
    }
    // epilogue: halo cols (left wx=1 <-> w0-1, right wx=34 <-> w0+32); 288 el.
    for (int idx = tid; idx < C_ * HH_ * 2; idx += NTHREADS) {
        int c    = idx / (HH_ * 2);
        int rem  = idx - c * (HH_ * 2);
        int row  = rem >> 1;
        int side = rem & 1;
        int gh   = h0 - 1 + row;
        int gw   = side ? (w0 + 32) : (w0 - 1);
        float p = 0.0f, lp = -1e9f;
        if (((unsigned)gh < H_) && ((unsigned)gw < W_)) {
            float x = cmap[((long)(b * C_ + c) * H_ + gh) * W_ + gw];
            sigmoid_pair(x, p, lp);
        }
        int si = (c * HH_ + row) * SROW + (side ? 34 : 1);
        s_p[si]  = p;
        s_lp[si] = lp;
    }
    __syncthreads();

    // ==== compute phase: 1 px/lane, 2 rows/thread; conflict-free LDS.
    // vote k: center ch k x ch 7-k at neighbor (DH[k],DW[k]).
    // Selected votes: lv = clip(lpc+nlp) (log of product, free).
    // Unselected: sum log(1-v) = log(prod(1-v)), never clips (1-v >= ~0.01).
    const int DH[8] = {-1, -1, -1,  0, 0,  1, 1, 1};
    const int DW[8] = {-1,  0,  1, -1, 1, -1, 0, 1};

    #pragma unroll
    for (int q = 0; q < 2; q++) {
        const int py = wrp + q * 8;          // tile row 0..15
        const int gh = h0 + py;
        const int gw = w0 + lane;
        const int sbase = (py + 1) * SROW + lane + 2;
        const unsigned mask = s_mask[py * TW + lane];

        float pc[8], lpc[8];
        #pragma unroll
        for (int c = 0; c < 8; c++) {
            int si = c * (HH_ * SROW) + sbase;
            pc[c]  = s_p[si];
            lpc[c] = s_lp[si];
        }

        float vmin = 1e30f, vsum = 0.0f, prod = 1.0f;
        #pragma unroll
        for (int k = 0; k < 8; k++) {
            int ni = (7 - k) * (HH_ * SROW) + (py + 1 + DH[k]) * SROW
                     + (lane + 2 + DW[k]);
            float np  = s_p[ni];
            float nlp = s_lp[ni];
            float v   = pc[k] * np;
            float omv = fmaf(-pc[k], np, 1.0f);              // 1 - v
            float lv  = fmaxf(lpc[k] + nlp, -100.0f);        // log(pa*pb), free
            bool  bit = (mask >> k) & 1u;
            acc02 += bit ? lv : 0.0f;
            prod  *= bit ? 1.0f : omv;                       // defer the log
            vmin = fminf(vmin, v);
            vsum += v;
        }
        acc02 += __logf(prod);

        // decouple / de loss (w=1.0): one logf via argument select
        bool  edge = (mask != 0u) && (mask != 0xFFu);
        float glo  = vsum * 0.125f;
        float da   = edge ? (1.0f - vmin) : glo;            // decouple_map
        float db   = edge ? vmin : (1.0f - glo);            // 1 - decouple_map
        float tt   = __ldcs(&target[((size_t)b * H_ + gh) * W_ + gw]);
        float arg  = (tt != 0.0f) ? da : db;
        acc1 += fmaxf(__logf(arg), -100.0f);
    }

    // ==== block reduction + global accumulate ==============================
    float acc = fmaf(0.8f, acc08, fmaf(0.2f, acc02, acc1));
    #pragma unroll
    for (int off = 16; off; off >>= 1)
        acc += __shfl_xor_sync(0xFFFFFFFFu, acc, off);

    __shared__ float warpsum[8];
    if (lane == 0) warpsum[wrp] = acc;
    __syncthreads();
    if (tid < 8) {
        float v = warpsum[tid];
        #pragma unroll
        for (int off = 4; off; off >>= 1)
            v += __shfl_xor_sync(0xFFu, v, off);
        if (tid == 0) atomicAdd(&g_acc, (double)v);
    }

    // ==== last block finalizes: write out, reset for next graph replay =====
    if (tid == 0) {
        __threadfence();
        unsigned t = atomicAdd(&g_tick, 1u);
        if (t == (unsigned)(NBLOCKS - 1)) {
            __threadfence();
            double total = atomicAdd(&g_acc, 0.0);
            out[0] = (float)(-total);
            g_acc  = 0.0;
            g_tick = 0u;
            __threadfence();
        }
    }
}

extern "C" void kernel_launch(void* const* d_in, const int* in_sizes, int n_in,
                              void* d_out, int out_size) {
    const float* cmap   = (const float*)d_in[0];
    const float* target = (const float*)d_in[1];
    const float* con    = (const float*)d_in[2];

    dim3 grid(W_ / TW, H_ / TH, B_);
    k_main<<<grid, NTHREADS>>>(cmap, target, con, (float*)d_out);
}